// round 7
// baseline (speedup 1.0000x reference)
#include <cuda_runtime.h>
#include <math.h>
#include <stdint.h>

// Problem constants
#define B_   2
#define T_   16
#define H_   56
#define W_   56
#define C_   128
#define NC   512
#define VOL  98
#define NH   4
#define HD   32

// Tiling / strides
#define MP   112         // padded rows (7 x 16)
#define NP   104         // padded j (13 x 8)
#define RNST 132         // rn row stride (A operand, 4g+c conflict-free)
#define QST  36          // q row stride
#define KTST 104         // kT row stride (8c+g)
#define VST  40          // v row stride (8c+g)
#define PST  108         // p row stride (12g+c)
#define BQST 40          // qkv B-chunk stride (8c+g)
#define BPST 136         // proj B stride (8c+g)

// smem element offsets (uint32 units)
#define OFF_RN   0
#define OFF_Q    (OFF_RN + MP*RNST)     // 14784
#define OFF_KT   (OFF_Q  + MP*QST)      // +4032
#define OFF_V    (OFF_KT + 32*KTST)     // +3328
#define OFF_P    (OFF_V  + NP*VST)      // +4160
#define OFF_RID  (OFF_P  + MP*PST)      // +12096
#define SMEM_U32 (OFF_RID + MP)
#define SMEM_BYTES (SMEM_U32 * 4)       // 154496 B

__device__ __forceinline__ uint32_t f2tf32(float f) {
    uint32_t u;
    asm("cvt.rna.tf32.f32 %0, %1;" : "=r"(u) : "f"(f));
    return u;
}

__device__ __forceinline__ void mma_tf32(float* acc, const uint32_t* a, const uint32_t* b) {
    asm volatile(
        "mma.sync.aligned.m16n8k8.row.col.f32.tf32.tf32.f32 "
        "{%0,%1,%2,%3}, {%4,%5,%6,%7}, {%8,%9}, {%0,%1,%2,%3};\n"
        : "+f"(acc[0]), "+f"(acc[1]), "+f"(acc[2]), "+f"(acc[3])
        : "r"(a[0]), "r"(a[1]), "r"(a[2]), "r"(a[3]),
          "r"(b[0]), "r"(b[1]));
}

__global__ __launch_bounds__(224, 1)
void fused_layer(const float* __restrict__ x,
                 const float* __restrict__ gamma,
                 const float* __restrict__ beta,
                 const float* __restrict__ w_qkv,
                 const float* __restrict__ w_proj,
                 const float* __restrict__ b_proj,
                 float* __restrict__ out)
{
    extern __shared__ uint32_t sm[];
    uint32_t* rn  = sm + OFF_RN;    // [112][132]  LN'd input tf32 -> later proj A (o)
    uint32_t* q   = sm + OFF_Q;     // [112][36]
    uint32_t* kT  = sm + OFF_KT;    // [32][104]
    uint32_t* v   = sm + OFF_V;     // [104][40]
    uint32_t* p   = sm + OFF_P;     // [112][108] floats (exp'd probs, tf32 bits)
    int*      rid = (int*)(sm + OFF_RID);
    uint32_t* BsQ = p;              // [128][40]  alias of p
    uint32_t* BsP = q;              // [128][136] alias of q..p
    float*    pf  = (float*)p;
    float*    rnf = (float*)rn;

    int cn  = blockIdx.x;
    int b   = cn >> 9;
    int n   = cn & (NC - 1);
    int tid = threadIdx.x;
    int wid = tid >> 5, lane = tid & 31;
    int g = lane >> 2, c = lane & 3;

    int bt = n >> 6, bh = (n >> 3) & 7, bw = n & 7;

    // ---------------- Phase A: gather x rows (roll + reorder), raw floats ----
    for (int idx = tid; idx < MP * 32; idx += 224) {
        int i  = idx >> 5;
        int l4 = (idx & 31) << 2;
        float4 xv = make_float4(0.f, 0.f, 0.f, 0.f);
        if (i < VOL) {
            int lt = i / 49, r2 = i % 49, lh = r2 / 7, lw = r2 % 7;
            int t  = (2 * bt + lt + 1) & (T_ - 1);
            int hh = 7 * bh + lh + 3; if (hh >= H_) hh -= H_;
            int ww = 7 * bw + lw + 3; if (ww >= W_) ww -= W_;
            size_t off = (((size_t)(b * T_ + t) * H_ + hh) * W_ + ww) * C_ + l4;
            xv = *(const float4*)(x + off);
        }
        *(float4*)(rnf + i * RNST + l4) = xv;
    }
    // region ids
    if (tid < MP) {
        int i = tid;
        if (i < VOL) {
            int lt = i / 49, r2 = i % 49, lh = r2 / 7, lw = r2 % 7;
            int rt = (bt == 7) ? (lt == 0 ? 1 : 2) : 0;
            int rh = (bh == 7) ? (lh < 4 ? 1 : 2) : 0;
            int rw = (bw == 7) ? (lw < 4 ? 1 : 2) : 0;
            rid[i] = rt * 9 + rh * 3 + rw;
        } else {
            rid[i] = -1;
        }
    }
    __syncthreads();

    // ---------------- Phase B: LayerNorm rows in place, convert to tf32 -----
    {
        float4 gm = *(const float4*)(gamma + 4 * lane);
        float4 be = *(const float4*)(beta  + 4 * lane);
        for (int i = wid; i < VOL; i += 7) {
            float* row = rnf + i * RNST;
            float4 xv = *(float4*)(row + 4 * lane);
            float s  = xv.x + xv.y + xv.z + xv.w;
            float ss = xv.x*xv.x + xv.y*xv.y + xv.z*xv.z + xv.w*xv.w;
            #pragma unroll
            for (int o = 16; o > 0; o >>= 1) {
                s  += __shfl_xor_sync(0xffffffffu, s,  o);
                ss += __shfl_xor_sync(0xffffffffu, ss, o);
            }
            float mean = s * (1.0f / C_);
            float var  = ss * (1.0f / C_) - mean * mean;
            float rstd = rsqrtf(var + 1e-5f);
            uint4 u;
            u.x = f2tf32((xv.x - mean) * rstd * gm.x + be.x);
            u.y = f2tf32((xv.y - mean) * rstd * gm.y + be.y);
            u.z = f2tf32((xv.z - mean) * rstd * gm.z + be.z);
            u.w = f2tf32((xv.w - mean) * rstd * gm.w + be.w);
            *(uint4*)((uint32_t*)row + 4 * lane) = u;
        }
        // pad rows 98..111: convert zeros to tf32 zeros (already 0 bits) - nothing needed
    }

    int r0 = wid * 16 + g, r1 = r0 + 8;
    float o_regs[64];

    // ---------------- Head loop: qkv chunk-gemms + attention -----------------
    for (int h = 0; h < 4; h++) {
        #pragma unroll
        for (int chunk = 0; chunk < 3; chunk++) {
            __syncthreads();   // prior users of BsQ/p and q/kT/v done
            // load B chunk [128][32] -> BsQ [128][40]
            int cb = chunk * 128 + h * 32;
            for (int idx = tid; idx < 1024; idx += 224) {
                int r = idx >> 3, c4 = (idx & 7) << 2;
                float4 b4 = *(const float4*)(w_qkv + (size_t)r * 384 + cb + c4);
                uint4 u = make_uint4(f2tf32(b4.x), f2tf32(b4.y), f2tf32(b4.z), f2tf32(b4.w));
                BsQ[r * BQST + c4 + 0] = u.x;
                BsQ[r * BQST + c4 + 1] = u.y;
                BsQ[r * BQST + c4 + 2] = u.z;
                BsQ[r * BQST + c4 + 3] = u.w;
            }
            __syncthreads();

            // gemm: rows r0/r1 x 32 cols, K=128
            float acc[4][4] = {};
            #pragma unroll
            for (int kst = 0; kst < 16; kst++) {
                int kk = kst << 3;
                uint32_t a[4];
                a[0] = rn[r0 * RNST + kk + c];
                a[1] = rn[r1 * RNST + kk + c];
                a[2] = rn[r0 * RNST + kk + c + 4];
                a[3] = rn[r1 * RNST + kk + c + 4];
                #pragma unroll
                for (int nt = 0; nt < 4; nt++) {
                    uint32_t bf[2];
                    bf[0] = BsQ[(kk + c) * BQST + nt * 8 + g];
                    bf[1] = BsQ[(kk + c + 4) * BQST + nt * 8 + g];
                    mma_tf32(acc[nt], a, bf);
                }
            }
            // store into attention layouts
            if (chunk == 0) {
                const float s = 0.17677669529663687f;  // hd^-0.5
                #pragma unroll
                for (int nt = 0; nt < 4; nt++) {
                    int col = nt * 8 + 2 * c;
                    q[r0 * QST + col]     = f2tf32(acc[nt][0] * s);
                    q[r0 * QST + col + 1] = f2tf32(acc[nt][1] * s);
                    q[r1 * QST + col]     = f2tf32(acc[nt][2] * s);
                    q[r1 * QST + col + 1] = f2tf32(acc[nt][3] * s);
                }
            } else if (chunk == 1) {
                #pragma unroll
                for (int nt = 0; nt < 4; nt++) {
                    int d = nt * 8 + 2 * c;
                    if (r0 < NP) {
                        kT[d * KTST + r0]       = f2tf32(acc[nt][0]);
                        kT[(d + 1) * KTST + r0] = f2tf32(acc[nt][1]);
                    }
                    if (r1 < NP) {
                        kT[d * KTST + r1]       = f2tf32(acc[nt][2]);
                        kT[(d + 1) * KTST + r1] = f2tf32(acc[nt][3]);
                    }
                }
            } else {
                #pragma unroll
                for (int nt = 0; nt < 4; nt++) {
                    int d = nt * 8 + 2 * c;
                    if (r0 < NP) {
                        v[r0 * VST + d]     = f2tf32(acc[nt][0]);
                        v[r0 * VST + d + 1] = f2tf32(acc[nt][1]);
                    }
                    if (r1 < NP) {
                        v[r1 * VST + d]     = f2tf32(acc[nt][2]);
                        v[r1 * VST + d + 1] = f2tf32(acc[nt][3]);
                    }
                }
            }
        }
        __syncthreads();   // q/kT/v visible to all warps

        // ---- attention: warp-owned 16-row stripe ----
        int ri0 = rid[r0], ri1 = rid[r1];
        uint32_t aq[4][4];
        #pragma unroll
        for (int ks = 0; ks < 4; ks++) {
            int kk = ks << 3;
            aq[ks][0] = q[r0 * QST + kk + c];
            aq[ks][1] = q[r1 * QST + kk + c];
            aq[ks][2] = q[r0 * QST + kk + c + 4];
            aq[ks][3] = q[r1 * QST + kk + c + 4];
        }

        float s0 = 0.f, s1 = 0.f;
        #pragma unroll
        for (int nt = 0; nt < 13; nt++) {
            int n0 = nt << 3;
            float acc[4] = {0.f, 0.f, 0.f, 0.f};
            #pragma unroll
            for (int ks = 0; ks < 4; ks++) {
                int kk = ks << 3;
                uint32_t bf[2];
                bf[0] = kT[(kk + c) * KTST + n0 + g];
                bf[1] = kT[(kk + c + 4) * KTST + n0 + g];
                mma_tf32(acc, aq[ks], bf);
            }
            int col = n0 + 2 * c;
            int rj0 = rid[col], rj1 = rid[col + 1];
            float e0 = (ri0 == rj0) ? __expf(fminf(acc[0], 80.f)) : 0.f;
            float e1 = (ri0 == rj1) ? __expf(fminf(acc[1], 80.f)) : 0.f;
            float e2 = (ri1 == rj0) ? __expf(fminf(acc[2], 80.f)) : 0.f;
            float e3 = (ri1 == rj1) ? __expf(fminf(acc[3], 80.f)) : 0.f;
            s0 += e0 + e1;
            s1 += e2 + e3;
            pf[r0 * PST + col]     = __uint_as_float(f2tf32(e0));
            pf[r0 * PST + col + 1] = __uint_as_float(f2tf32(e1));
            pf[r1 * PST + col]     = __uint_as_float(f2tf32(e2));
            pf[r1 * PST + col + 1] = __uint_as_float(f2tf32(e3));
        }
        s0 += __shfl_xor_sync(0xffffffffu, s0, 1);
        s0 += __shfl_xor_sync(0xffffffffu, s0, 2);
        s1 += __shfl_xor_sync(0xffffffffu, s1, 1);
        s1 += __shfl_xor_sync(0xffffffffu, s1, 2);
        float rinv0 = 1.0f / s0;
        float rinv1 = 1.0f / s1;
        __syncwarp();

        // AV into registers
        #pragma unroll
        for (int nt = 0; nt < 4; nt++) {
            int d0 = nt << 3;
            float acc[4] = {0.f, 0.f, 0.f, 0.f};
            #pragma unroll
            for (int ks = 0; ks < 13; ks++) {
                int kk = ks << 3;
                uint32_t a[4], bf[2];
                a[0] = p[r0 * PST + kk + c];
                a[1] = p[r1 * PST + kk + c];
                a[2] = p[r0 * PST + kk + c + 4];
                a[3] = p[r1 * PST + kk + c + 4];
                bf[0] = v[(kk + c) * VST + d0 + g];
                bf[1] = v[(kk + c + 4) * VST + d0 + g];
                mma_tf32(acc, a, bf);
            }
            o_regs[h * 16 + nt * 4 + 0] = acc[0] * rinv0;
            o_regs[h * 16 + nt * 4 + 1] = acc[1] * rinv0;
            o_regs[h * 16 + nt * 4 + 2] = acc[2] * rinv1;
            o_regs[h * 16 + nt * 4 + 3] = acc[3] * rinv1;
        }
    }

    // ---------------- o_regs -> rn (proj A operand); load w_proj -------------
    __syncthreads();   // attention fully done; q..p free for BsP; rn free for o
    #pragma unroll
    for (int h = 0; h < 4; h++)
        #pragma unroll
        for (int nt = 0; nt < 4; nt++) {
            int col = h * 32 + nt * 8 + 2 * c;
            rn[r0 * RNST + col]     = f2tf32(o_regs[h * 16 + nt * 4 + 0]);
            rn[r0 * RNST + col + 1] = f2tf32(o_regs[h * 16 + nt * 4 + 1]);
            rn[r1 * RNST + col]     = f2tf32(o_regs[h * 16 + nt * 4 + 2]);
            rn[r1 * RNST + col + 1] = f2tf32(o_regs[h * 16 + nt * 4 + 3]);
        }
    for (int idx = tid; idx < 4096; idx += 224) {
        int r = idx >> 5, c4 = (idx & 31) << 2;
        float4 b4 = *(const float4*)(w_proj + (size_t)r * 128 + c4);
        uint4 u = make_uint4(f2tf32(b4.x), f2tf32(b4.y), f2tf32(b4.z), f2tf32(b4.w));
        BsP[r * BPST + c4 + 0] = u.x;
        BsP[r * BPST + c4 + 1] = u.y;
        BsP[r * BPST + c4 + 2] = u.z;
        BsP[r * BPST + c4 + 3] = u.w;
    }
    __syncthreads();

    // ---------------- proj gemm + scatter -----------------------------------
    float pacc[16][4] = {};
    #pragma unroll
    for (int kst = 0; kst < 16; kst++) {
        int kk = kst << 3;
        uint32_t a[4];
        a[0] = rn[r0 * RNST + kk + c];
        a[1] = rn[r1 * RNST + kk + c];
        a[2] = rn[r0 * RNST + kk + c + 4];
        a[3] = rn[r1 * RNST + kk + c + 4];
        #pragma unroll
        for (int nt = 0; nt < 16; nt++) {
            uint32_t bf[2];
            bf[0] = BsP[(kk + c) * BPST + nt * 8 + g];
            bf[1] = BsP[(kk + c + 4) * BPST + nt * 8 + g];
            mma_tf32(pacc[nt], a, bf);
        }
    }

    // scatter with reverse reorder + roll(+1,+3,+3)
    size_t off0 = 0, off1 = 0;
    if (r0 < VOL) {
        int i = r0;
        int lt = i / 49, r2 = i % 49, lh = r2 / 7, lw = r2 % 7;
        int t  = (2 * bt + lt + 1) & (T_ - 1);
        int hh = 7 * bh + lh + 3; if (hh >= H_) hh -= H_;
        int ww = 7 * bw + lw + 3; if (ww >= W_) ww -= W_;
        off0 = (((size_t)(b * T_ + t) * H_ + hh) * W_ + ww) * C_;
    }
    if (r1 < VOL) {
        int i = r1;
        int lt = i / 49, r2 = i % 49, lh = r2 / 7, lw = r2 % 7;
        int t  = (2 * bt + lt + 1) & (T_ - 1);
        int hh = 7 * bh + lh + 3; if (hh >= H_) hh -= H_;
        int ww = 7 * bw + lw + 3; if (ww >= W_) ww -= W_;
        off1 = (((size_t)(b * T_ + t) * H_ + hh) * W_ + ww) * C_;
    }
    #pragma unroll
    for (int nt = 0; nt < 16; nt++) {
        int col = nt * 8 + 2 * c;
        float2 bb = *(const float2*)(b_proj + col);
        if (r0 < VOL)
            *(float2*)(out + off0 + col) =
                make_float2(pacc[nt][0] + bb.x, pacc[nt][1] + bb.y);
        if (r1 < VOL)
            *(float2*)(out + off1 + col) =
                make_float2(pacc[nt][2] + bb.x, pacc[nt][3] + bb.y);
    }
}

// ---------------------------------------------------------------------------
extern "C" void kernel_launch(void* const* d_in, const int* in_sizes, int n_in,
                              void* d_out, int out_size)
{
    const float* x      = (const float*)d_in[0];
    const float* gamma  = (const float*)d_in[1];
    const float* beta   = (const float*)d_in[2];
    const float* w_qkv  = (const float*)d_in[3];
    const float* w_proj = (const float*)d_in[4];
    const float* b_proj = (const float*)d_in[5];
    float* out = (float*)d_out;

    cudaFuncSetAttribute(fused_layer, cudaFuncAttributeMaxDynamicSharedMemorySize, SMEM_BYTES);
    fused_layer<<<B_ * NC, 224, SMEM_BYTES>>>(x, gamma, beta, w_qkv, w_proj, b_proj, out);
}

// round 8
// speedup vs baseline: 1.0001x; 1.0001x over previous
#include <cuda_runtime.h>
#include <math.h>
#include <stdint.h>

// Problem constants
#define B_   2
#define T_   16
#define H_   56
#define W_   56
#define C_   128
#define NC   512
#define VOL  98
#define NH   4
#define HD   32

// Tiling / strides
#define MP   112         // padded rows (7 x 16)
#define NP   104         // padded j (13 x 8)
#define RNST 132         // rn row stride (A operand, 4g+c conflict-free)
#define QST  36          // q row stride
#define KTST 104         // kT row stride (8c+g)
#define VST  40          // v row stride (8c+g)
#define PST  108         // p row stride (12g+c)
#define BQST 40          // qkv B-chunk stride (8c+g)
#define BPST 136         // proj B stride (8c+g)

// smem element offsets (uint32 units)
#define OFF_RN   0
#define OFF_Q    (OFF_RN + MP*RNST)     // 14784
#define OFF_KT   (OFF_Q  + MP*QST)      // +4032
#define OFF_V    (OFF_KT + 32*KTST)     // +3328
#define OFF_P    (OFF_V  + NP*VST)      // +4160
#define OFF_RID  (OFF_P  + MP*PST)      // +12096
#define SMEM_U32 (OFF_RID + MP)
#define SMEM_BYTES (SMEM_U32 * 4)       // 154496 B

__device__ __forceinline__ uint32_t f2tf32(float f) {
    uint32_t u;
    asm("cvt.rna.tf32.f32 %0, %1;" : "=r"(u) : "f"(f));
    return u;
}

__device__ __forceinline__ void mma_tf32(float* acc, const uint32_t* a, const uint32_t* b) {
    asm volatile(
        "mma.sync.aligned.m16n8k8.row.col.f32.tf32.tf32.f32 "
        "{%0,%1,%2,%3}, {%4,%5,%6,%7}, {%8,%9}, {%0,%1,%2,%3};\n"
        : "+f"(acc[0]), "+f"(acc[1]), "+f"(acc[2]), "+f"(acc[3])
        : "r"(a[0]), "r"(a[1]), "r"(a[2]), "r"(a[3]),
          "r"(b[0]), "r"(b[1]));
}

__global__ __launch_bounds__(224, 1)
void fused_layer(const float* __restrict__ x,
                 const float* __restrict__ gamma,
                 const float* __restrict__ beta,
                 const float* __restrict__ w_qkv,
                 const float* __restrict__ w_proj,
                 const float* __restrict__ b_proj,
                 float* __restrict__ out)
{
    extern __shared__ uint32_t sm[];
    uint32_t* rn  = sm + OFF_RN;    // [112][132]  LN'd input tf32 -> later proj A (o)
    uint32_t* q   = sm + OFF_Q;     // [112][36]
    uint32_t* kT  = sm + OFF_KT;    // [32][104]
    uint32_t* v   = sm + OFF_V;     // [104][40]
    uint32_t* p   = sm + OFF_P;     // [112][108] floats (exp'd probs, tf32 bits)
    int*      rid = (int*)(sm + OFF_RID);
    uint32_t* BsQ = p;              // [128][40]  alias of p
    uint32_t* BsP = q;              // [128][136] alias of q..p
    float*    pf  = (float*)p;
    float*    rnf = (float*)rn;

    int cn  = blockIdx.x;
    int b   = cn >> 9;
    int n   = cn & (NC - 1);
    int tid = threadIdx.x;
    int wid = tid >> 5, lane = tid & 31;
    int g = lane >> 2, c = lane & 3;

    int bt = n >> 6, bh = (n >> 3) & 7, bw = n & 7;

    // ---------------- Phase A: gather x rows (roll + reorder), raw floats ----
    for (int idx = tid; idx < MP * 32; idx += 224) {
        int i  = idx >> 5;
        int l4 = (idx & 31) << 2;
        float4 xv = make_float4(0.f, 0.f, 0.f, 0.f);
        if (i < VOL) {
            int lt = i / 49, r2 = i % 49, lh = r2 / 7, lw = r2 % 7;
            int t  = (2 * bt + lt + 1) & (T_ - 1);
            int hh = 7 * bh + lh + 3; if (hh >= H_) hh -= H_;
            int ww = 7 * bw + lw + 3; if (ww >= W_) ww -= W_;
            size_t off = (((size_t)(b * T_ + t) * H_ + hh) * W_ + ww) * C_ + l4;
            xv = *(const float4*)(x + off);
        }
        *(float4*)(rnf + i * RNST + l4) = xv;
    }
    // region ids
    if (tid < MP) {
        int i = tid;
        if (i < VOL) {
            int lt = i / 49, r2 = i % 49, lh = r2 / 7, lw = r2 % 7;
            int rt = (bt == 7) ? (lt == 0 ? 1 : 2) : 0;
            int rh = (bh == 7) ? (lh < 4 ? 1 : 2) : 0;
            int rw = (bw == 7) ? (lw < 4 ? 1 : 2) : 0;
            rid[i] = rt * 9 + rh * 3 + rw;
        } else {
            rid[i] = -1;
        }
    }
    __syncthreads();

    // ---------------- Phase B: LayerNorm rows in place, convert to tf32 -----
    {
        float4 gm = *(const float4*)(gamma + 4 * lane);
        float4 be = *(const float4*)(beta  + 4 * lane);
        for (int i = wid; i < VOL; i += 7) {
            float* row = rnf + i * RNST;
            float4 xv = *(float4*)(row + 4 * lane);
            float s  = xv.x + xv.y + xv.z + xv.w;
            float ss = xv.x*xv.x + xv.y*xv.y + xv.z*xv.z + xv.w*xv.w;
            #pragma unroll
            for (int o = 16; o > 0; o >>= 1) {
                s  += __shfl_xor_sync(0xffffffffu, s,  o);
                ss += __shfl_xor_sync(0xffffffffu, ss, o);
            }
            float mean = s * (1.0f / C_);
            float var  = ss * (1.0f / C_) - mean * mean;
            float rstd = rsqrtf(var + 1e-5f);
            uint4 u;
            u.x = f2tf32((xv.x - mean) * rstd * gm.x + be.x);
            u.y = f2tf32((xv.y - mean) * rstd * gm.y + be.y);
            u.z = f2tf32((xv.z - mean) * rstd * gm.z + be.z);
            u.w = f2tf32((xv.w - mean) * rstd * gm.w + be.w);
            *(uint4*)((uint32_t*)row + 4 * lane) = u;
        }
        // pad rows 98..111: convert zeros to tf32 zeros (already 0 bits) - nothing needed
    }

    int r0 = wid * 16 + g, r1 = r0 + 8;
    float o_regs[64];

    // ---------------- Head loop: qkv chunk-gemms + attention -----------------
    for (int h = 0; h < 4; h++) {
        #pragma unroll
        for (int chunk = 0; chunk < 3; chunk++) {
            __syncthreads();   // prior users of BsQ/p and q/kT/v done
            // load B chunk [128][32] -> BsQ [128][40]
            int cb = chunk * 128 + h * 32;
            for (int idx = tid; idx < 1024; idx += 224) {
                int r = idx >> 3, c4 = (idx & 7) << 2;
                float4 b4 = *(const float4*)(w_qkv + (size_t)r * 384 + cb + c4);
                uint4 u = make_uint4(f2tf32(b4.x), f2tf32(b4.y), f2tf32(b4.z), f2tf32(b4.w));
                BsQ[r * BQST + c4 + 0] = u.x;
                BsQ[r * BQST + c4 + 1] = u.y;
                BsQ[r * BQST + c4 + 2] = u.z;
                BsQ[r * BQST + c4 + 3] = u.w;
            }
            __syncthreads();

            // gemm: rows r0/r1 x 32 cols, K=128
            float acc[4][4] = {};
            #pragma unroll
            for (int kst = 0; kst < 16; kst++) {
                int kk = kst << 3;
                uint32_t a[4];
                a[0] = rn[r0 * RNST + kk + c];
                a[1] = rn[r1 * RNST + kk + c];
                a[2] = rn[r0 * RNST + kk + c + 4];
                a[3] = rn[r1 * RNST + kk + c + 4];
                #pragma unroll
                for (int nt = 0; nt < 4; nt++) {
                    uint32_t bf[2];
                    bf[0] = BsQ[(kk + c) * BQST + nt * 8 + g];
                    bf[1] = BsQ[(kk + c + 4) * BQST + nt * 8 + g];
                    mma_tf32(acc[nt], a, bf);
                }
            }
            // store into attention layouts
            if (chunk == 0) {
                const float s = 0.17677669529663687f;  // hd^-0.5
                #pragma unroll
                for (int nt = 0; nt < 4; nt++) {
                    int col = nt * 8 + 2 * c;
                    q[r0 * QST + col]     = f2tf32(acc[nt][0] * s);
                    q[r0 * QST + col + 1] = f2tf32(acc[nt][1] * s);
                    q[r1 * QST + col]     = f2tf32(acc[nt][2] * s);
                    q[r1 * QST + col + 1] = f2tf32(acc[nt][3] * s);
                }
            } else if (chunk == 1) {
                #pragma unroll
                for (int nt = 0; nt < 4; nt++) {
                    int d = nt * 8 + 2 * c;
                    if (r0 < NP) {
                        kT[d * KTST + r0]       = f2tf32(acc[nt][0]);
                        kT[(d + 1) * KTST + r0] = f2tf32(acc[nt][1]);
                    }
                    if (r1 < NP) {
                        kT[d * KTST + r1]       = f2tf32(acc[nt][2]);
                        kT[(d + 1) * KTST + r1] = f2tf32(acc[nt][3]);
                    }
                }
            } else {
                #pragma unroll
                for (int nt = 0; nt < 4; nt++) {
                    int d = nt * 8 + 2 * c;
                    if (r0 < NP) {
                        v[r0 * VST + d]     = f2tf32(acc[nt][0]);
                        v[r0 * VST + d + 1] = f2tf32(acc[nt][1]);
                    }
                    if (r1 < NP) {
                        v[r1 * VST + d]     = f2tf32(acc[nt][2]);
                        v[r1 * VST + d + 1] = f2tf32(acc[nt][3]);
                    }
                }
            }
        }
        __syncthreads();   // q/kT/v visible to all warps

        // ---- attention: warp-owned 16-row stripe ----
        int ri0 = rid[r0], ri1 = rid[r1];
        uint32_t aq[4][4];
        #pragma unroll
        for (int ks = 0; ks < 4; ks++) {
            int kk = ks << 3;
            aq[ks][0] = q[r0 * QST + kk + c];
            aq[ks][1] = q[r1 * QST + kk + c];
            aq[ks][2] = q[r0 * QST + kk + c + 4];
            aq[ks][3] = q[r1 * QST + kk + c + 4];
        }

        float s0 = 0.f, s1 = 0.f;
        #pragma unroll
        for (int nt = 0; nt < 13; nt++) {
            int n0 = nt << 3;
            float acc[4] = {0.f, 0.f, 0.f, 0.f};
            #pragma unroll
            for (int ks = 0; ks < 4; ks++) {
                int kk = ks << 3;
                uint32_t bf[2];
                bf[0] = kT[(kk + c) * KTST + n0 + g];
                bf[1] = kT[(kk + c + 4) * KTST + n0 + g];
                mma_tf32(acc, aq[ks], bf);
            }
            int col = n0 + 2 * c;
            int rj0 = rid[col], rj1 = rid[col + 1];
            float e0 = (ri0 == rj0) ? __expf(fminf(acc[0], 80.f)) : 0.f;
            float e1 = (ri0 == rj1) ? __expf(fminf(acc[1], 80.f)) : 0.f;
            float e2 = (ri1 == rj0) ? __expf(fminf(acc[2], 80.f)) : 0.f;
            float e3 = (ri1 == rj1) ? __expf(fminf(acc[3], 80.f)) : 0.f;
            s0 += e0 + e1;
            s1 += e2 + e3;
            pf[r0 * PST + col]     = __uint_as_float(f2tf32(e0));
            pf[r0 * PST + col + 1] = __uint_as_float(f2tf32(e1));
            pf[r1 * PST + col]     = __uint_as_float(f2tf32(e2));
            pf[r1 * PST + col + 1] = __uint_as_float(f2tf32(e3));
        }
        s0 += __shfl_xor_sync(0xffffffffu, s0, 1);
        s0 += __shfl_xor_sync(0xffffffffu, s0, 2);
        s1 += __shfl_xor_sync(0xffffffffu, s1, 1);
        s1 += __shfl_xor_sync(0xffffffffu, s1, 2);
        float rinv0 = 1.0f / s0;
        float rinv1 = 1.0f / s1;
        __syncwarp();

        // AV into registers
        #pragma unroll
        for (int nt = 0; nt < 4; nt++) {
            int d0 = nt << 3;
            float acc[4] = {0.f, 0.f, 0.f, 0.f};
            #pragma unroll
            for (int ks = 0; ks < 13; ks++) {
                int kk = ks << 3;
                uint32_t a[4], bf[2];
                a[0] = p[r0 * PST + kk + c];
                a[1] = p[r1 * PST + kk + c];
                a[2] = p[r0 * PST + kk + c + 4];
                a[3] = p[r1 * PST + kk + c + 4];
                bf[0] = v[(kk + c) * VST + d0 + g];
                bf[1] = v[(kk + c + 4) * VST + d0 + g];
                mma_tf32(acc, a, bf);
            }
            o_regs[h * 16 + nt * 4 + 0] = acc[0] * rinv0;
            o_regs[h * 16 + nt * 4 + 1] = acc[1] * rinv0;
            o_regs[h * 16 + nt * 4 + 2] = acc[2] * rinv1;
            o_regs[h * 16 + nt * 4 + 3] = acc[3] * rinv1;
        }
    }

    // ---------------- o_regs -> rn (proj A operand); load w_proj -------------
    __syncthreads();   // attention fully done; q..p free for BsP; rn free for o
    #pragma unroll
    for (int h = 0; h < 4; h++)
        #pragma unroll
        for (int nt = 0; nt < 4; nt++) {
            int col = h * 32 + nt * 8 + 2 * c;
            rn[r0 * RNST + col]     = f2tf32(o_regs[h * 16 + nt * 4 + 0]);
            rn[r0 * RNST + col + 1] = f2tf32(o_regs[h * 16 + nt * 4 + 1]);
            rn[r1 * RNST + col]     = f2tf32(o_regs[h * 16 + nt * 4 + 2]);
            rn[r1 * RNST + col + 1] = f2tf32(o_regs[h * 16 + nt * 4 + 3]);
        }
    for (int idx = tid; idx < 4096; idx += 224) {
        int r = idx >> 5, c4 = (idx & 31) << 2;
        float4 b4 = *(const float4*)(w_proj + (size_t)r * 128 + c4);
        uint4 u = make_uint4(f2tf32(b4.x), f2tf32(b4.y), f2tf32(b4.z), f2tf32(b4.w));
        BsP[r * BPST + c4 + 0] = u.x;
        BsP[r * BPST + c4 + 1] = u.y;
        BsP[r * BPST + c4 + 2] = u.z;
        BsP[r * BPST + c4 + 3] = u.w;
    }
    __syncthreads();

    // ---------------- proj gemm + scatter -----------------------------------
    float pacc[16][4] = {};
    #pragma unroll
    for (int kst = 0; kst < 16; kst++) {
        int kk = kst << 3;
        uint32_t a[4];
        a[0] = rn[r0 * RNST + kk + c];
        a[1] = rn[r1 * RNST + kk + c];
        a[2] = rn[r0 * RNST + kk + c + 4];
        a[3] = rn[r1 * RNST + kk + c + 4];
        #pragma unroll
        for (int nt = 0; nt < 16; nt++) {
            uint32_t bf[2];
            bf[0] = BsP[(kk + c) * BPST + nt * 8 + g];
            bf[1] = BsP[(kk + c + 4) * BPST + nt * 8 + g];
            mma_tf32(pacc[nt], a, bf);
        }
    }

    // scatter with reverse reorder + roll(+1,+3,+3)
    size_t off0 = 0, off1 = 0;
    if (r0 < VOL) {
        int i = r0;
        int lt = i / 49, r2 = i % 49, lh = r2 / 7, lw = r2 % 7;
        int t  = (2 * bt + lt + 1) & (T_ - 1);
        int hh = 7 * bh + lh + 3; if (hh >= H_) hh -= H_;
        int ww = 7 * bw + lw + 3; if (ww >= W_) ww -= W_;
        off0 = (((size_t)(b * T_ + t) * H_ + hh) * W_ + ww) * C_;
    }
    if (r1 < VOL) {
        int i = r1;
        int lt = i / 49, r2 = i % 49, lh = r2 / 7, lw = r2 % 7;
        int t  = (2 * bt + lt + 1) & (T_ - 1);
        int hh = 7 * bh + lh + 3; if (hh >= H_) hh -= H_;
        int ww = 7 * bw + lw + 3; if (ww >= W_) ww -= W_;
        off1 = (((size_t)(b * T_ + t) * H_ + hh) * W_ + ww) * C_;
    }
    #pragma unroll
    for (int nt = 0; nt < 16; nt++) {
        int col = nt * 8 + 2 * c;
        float2 bb = *(const float2*)(b_proj + col);
        if (r0 < VOL)
            *(float2*)(out + off0 + col) =
                make_float2(pacc[nt][0] + bb.x, pacc[nt][1] + bb.y);
        if (r1 < VOL)
            *(float2*)(out + off1 + col) =
                make_float2(pacc[nt][2] + bb.x, pacc[nt][3] + bb.y);
    }
}

// ---------------------------------------------------------------------------
extern "C" void kernel_launch(void* const* d_in, const int* in_sizes, int n_in,
                              void* d_out, int out_size)
{
    const float* x      = (const float*)d_in[0];
    const float* gamma  = (const float*)d_in[1];
    const float* beta   = (const float*)d_in[2];
    const float* w_qkv  = (const float*)d_in[3];
    const float* w_proj = (const float*)d_in[4];
    const float* b_proj = (const float*)d_in[5];
    float* out = (float*)d_out;

    cudaFuncSetAttribute(fused_layer, cudaFuncAttributeMaxDynamicSharedMemorySize, SMEM_BYTES);
    fused_layer<<<B_ * NC, 224, SMEM_BYTES>>>(x, gamma, beta, w_qkv, w_proj, b_proj, out);
}

// round 9
// speedup vs baseline: 1.5412x; 1.5410x over previous
#include <cuda_runtime.h>
#include <math.h>
#include <stdint.h>

// Problem constants
#define B_   2
#define T_   16
#define H_   56
#define W_   56
#define C_   128
#define NC   512
#define VOL  98
#define NH   4
#define HD   32
#define ROWS (B_*NC*VOL)   // 100352

// Shapes / strides
#define MP   112     // padded rows (7 x 16)
#define NP   104     // padded j (13 x 8)
#define QST  36
#define KTST 104
#define VST  40
#define PST  108
#define OST  132     // o overlay stride
#define BCST 40      // proj B chunk stride
#define AST  132     // qkv A tile stride

// attn_proj smem offsets (u32 units)
#define A_Q    0                      // 112*36  = 4032
#define A_KT   (A_Q  + MP*QST)        // +3328
#define A_V    (A_KT + 32*KTST)       // +4160
#define A_P    (A_V  + NP*VST)        // +12096
#define A_RID  (A_P  + MP*PST)        // 23616
#define AP_U32 (A_RID + MP)           // 23728 -> 94912 B
#define A_O    0                      // overlay: 112*132 = 14784
#define A_BC   (A_O + MP*OST)         // 14784..19904 (inside q..p, below rid)

__device__ float g_qkv[ROWS * 3 * C_];   // only remaining intermediate

__device__ __forceinline__ uint32_t f2tf32(float f) {
    uint32_t u;
    asm("cvt.rna.tf32.f32 %0, %1;" : "=r"(u) : "f"(f));
    return u;
}

__device__ __forceinline__ void mma_tf32(float* acc, const uint32_t* a, const uint32_t* b) {
    asm volatile(
        "mma.sync.aligned.m16n8k8.row.col.f32.tf32.tf32.f32 "
        "{%0,%1,%2,%3}, {%4,%5,%6,%7}, {%8,%9}, {%0,%1,%2,%3};\n"
        : "+f"(acc[0]), "+f"(acc[1]), "+f"(acc[2]), "+f"(acc[3])
        : "r"(a[0]), "r"(a[1]), "r"(a[2]), "r"(a[3]),
          "r"(b[0]), "r"(b[1]));
}

// gathered source offset for reordered row (b,n,i): roll(-1,-3,-3)+reorder fwd,
// equivalently out coordinate for reverse reorder + roll(+1,+3,+3).
__device__ __forceinline__ size_t src_off(int b, int bt, int bh, int bw, int i)
{
    int lt = i / 49, r2 = i % 49, lh = r2 / 7, lw = r2 % 7;
    int t  = (2 * bt + lt + 1) & (T_ - 1);
    int hh = 7 * bh + lh + 3; if (hh >= H_) hh -= H_;
    int ww = 7 * bw + lw + 3; if (ww >= W_) ww -= W_;
    return (((size_t)(b * T_ + t) * H_ + hh) * W_ + ww) * C_;
}

// ---------------------------------------------------------------------------
// Kernel 1: LN (fused gather) + QKV GEMM. A tile resident, 3 N-chunks.
// ---------------------------------------------------------------------------
__global__ __launch_bounds__(256, 2)
void qkv_ln_gemm(const float* __restrict__ x,
                 const float* __restrict__ gamma,
                 const float* __restrict__ beta,
                 const float* __restrict__ Bw)
{
    const int N = 384;
    extern __shared__ uint32_t qsm[];
    uint32_t* Af = qsm;                  // [128][132] LN'd A tile, tf32
    uint32_t* Bs = qsm + 128 * AST;      // [32][136]

    int tid = threadIdx.x;
    int bm = blockIdx.x << 7;
    int wid = tid >> 5, lane = tid & 31;
    int wm = wid & 3, wn = wid >> 2;
    int g = lane >> 2, c = lane & 3;

    // ---- A load: gather + LayerNorm (one warp per row) ----
    {
        float4 gm = *(const float4*)(gamma + 4 * lane);
        float4 be = *(const float4*)(beta  + 4 * lane);
        #pragma unroll 4
        for (int it = 0; it < 16; it++) {
            int rr   = it * 8 + wid;
            int grow = bm + rr;
            int b    = grow / (NC * VOL);
            int rem  = grow - b * (NC * VOL);
            int n    = rem / VOL;
            int i    = rem - n * VOL;
            int bt = n >> 6, bh = (n >> 3) & 7, bw = n & 7;
            const float4 xv = *(const float4*)(x + src_off(b, bt, bh, bw, i) + 4 * lane);
            float s  = xv.x + xv.y + xv.z + xv.w;
            float ss = xv.x*xv.x + xv.y*xv.y + xv.z*xv.z + xv.w*xv.w;
            #pragma unroll
            for (int o = 16; o > 0; o >>= 1) {
                s  += __shfl_xor_sync(0xffffffffu, s,  o);
                ss += __shfl_xor_sync(0xffffffffu, ss, o);
            }
            float mean = s * (1.0f / C_);
            float var  = ss * (1.0f / C_) - mean * mean;
            float rstd = rsqrtf(var + 1e-5f);
            uint4 u;
            u.x = f2tf32((xv.x - mean) * rstd * gm.x + be.x);
            u.y = f2tf32((xv.y - mean) * rstd * gm.y + be.y);
            u.z = f2tf32((xv.z - mean) * rstd * gm.z + be.z);
            u.w = f2tf32((xv.w - mean) * rstd * gm.w + be.w);
            *(uint4*)&Af[rr * AST + 4 * lane] = u;
        }
    }

    for (int bn = 0; bn < 3; bn++) {
        float acc[2][8][4] = {};
        for (int k0 = 0; k0 < 128; k0 += 32) {
            #pragma unroll
            for (int i = 0; i < 4; i++) {
                int idx = tid + 256 * i;
                int r = idx >> 5, c4 = (idx & 31) << 2;
                float4 b4 = *(const float4*)(Bw + (size_t)(k0 + r) * N + bn * 128 + c4);
                uint4 u = make_uint4(f2tf32(b4.x), f2tf32(b4.y), f2tf32(b4.z), f2tf32(b4.w));
                *(uint4*)&Bs[r * 136 + c4] = u;
            }
            __syncthreads();

            #pragma unroll
            for (int ks = 0; ks < 4; ks++) {
                int kk = k0 + (ks << 3);
                uint32_t a[2][4], b[8][2];
                #pragma unroll
                for (int m = 0; m < 2; m++) {
                    int row0 = wm * 32 + m * 16 + g;
                    a[m][0] = Af[row0 * AST + kk + c];
                    a[m][1] = Af[(row0 + 8) * AST + kk + c];
                    a[m][2] = Af[row0 * AST + kk + c + 4];
                    a[m][3] = Af[(row0 + 8) * AST + kk + c + 4];
                }
                int kl = ks << 3;
                #pragma unroll
                for (int nn = 0; nn < 8; nn++) {
                    int col = wn * 64 + nn * 8 + g;
                    b[nn][0] = Bs[(kl + c) * 136 + col];
                    b[nn][1] = Bs[(kl + c + 4) * 136 + col];
                }
                #pragma unroll
                for (int m = 0; m < 2; m++)
                    #pragma unroll
                    for (int nn = 0; nn < 8; nn++)
                        mma_tf32(acc[m][nn], a[m], b[nn]);
            }
            __syncthreads();
        }

        float scale = (bn == 0) ? 0.17677669529663687f : 1.0f;  // q * hd^-0.5
        #pragma unroll
        for (int m = 0; m < 2; m++) {
            int row = bm + wm * 32 + m * 16 + g;
            #pragma unroll
            for (int nn = 0; nn < 8; nn++) {
                int col = bn * 128 + wn * 64 + nn * 8 + 2 * c;
                float2 o0 = make_float2(acc[m][nn][0] * scale, acc[m][nn][1] * scale);
                float2 o1 = make_float2(acc[m][nn][2] * scale, acc[m][nn][3] * scale);
                *(float2*)(g_qkv + (size_t)row * 384 + col)       = o0;
                *(float2*)(g_qkv + (size_t)(row + 8) * 384 + col) = o1;
            }
        }
    }
}

// ---------------------------------------------------------------------------
// Kernel 2: attention (all 4 heads, warp-striped) + proj + scatter.
// One block per cuboid (grid 1024, 224 threads, 2 blocks/SM).
// ---------------------------------------------------------------------------
__global__ __launch_bounds__(224, 2)
void attn_proj(const float* __restrict__ w_proj,
               const float* __restrict__ b_proj,
               float* __restrict__ out)
{
    extern __shared__ uint32_t sm[];
    uint32_t* q   = sm + A_Q;      // [112][36]
    uint32_t* kT  = sm + A_KT;     // [32][104]
    uint32_t* v   = sm + A_V;      // [104][40]
    uint32_t* p   = sm + A_P;      // [112][108] warp-private stripes
    int*      rid = (int*)(sm + A_RID);
    uint32_t* o   = sm + A_O;      // overlay [112][132] (q..p dead by then)
    uint32_t* Bc  = sm + A_BC;     // overlay [128][40]
    float*    pf  = (float*)p;

    int cn  = blockIdx.x;
    int b   = cn >> 9;
    int n   = cn & (NC - 1);
    int tid = threadIdx.x;
    int wid = tid >> 5, lane = tid & 31;
    int g = lane >> 2, c = lane & 3;
    int bt = n >> 6, bh = (n >> 3) & 7, bw = n & 7;

    if (tid < MP) {
        int i = tid;
        if (i < VOL) {
            int lt = i / 49, r2 = i % 49, lh = r2 / 7, lw = r2 % 7;
            int rt = (bt == 7) ? (lt == 0 ? 1 : 2) : 0;
            int rh = (bh == 7) ? (lh < 4 ? 1 : 2) : 0;
            int rw = (bw == 7) ? (lw < 4 ? 1 : 2) : 0;
            rid[i] = rt * 9 + rh * 3 + rw;
        } else {
            rid[i] = -1;
        }
    }

    int r0 = wid * 16 + g, r1 = r0 + 8;
    size_t base = (size_t)(b * NC + n) * VOL * 384;
    float o_regs[64];

    for (int h = 0; h < 4; h++) {
        __syncthreads();   // prior head's kT/v reads done (and rid ready, h=0)
        #pragma unroll 4
        for (int idx = tid; idx < MP * 8; idx += 224) {
            int r  = idx >> 3;
            int c4 = (idx & 7) << 2;
            float4 qv = make_float4(0.f,0.f,0.f,0.f), kv = qv, vv = qv;
            if (r < VOL) {
                const float* src = g_qkv + base + (size_t)r * 384 + h * HD + c4;
                qv = *(const float4*)(src);
                kv = *(const float4*)(src + 128);
                vv = *(const float4*)(src + 256);
            }
            uint4 qu = make_uint4(f2tf32(qv.x), f2tf32(qv.y), f2tf32(qv.z), f2tf32(qv.w));
            *(uint4*)&q[r * QST + c4] = qu;
            if (r < NP) {
                kT[(c4 + 0) * KTST + r] = f2tf32(kv.x);
                kT[(c4 + 1) * KTST + r] = f2tf32(kv.y);
                kT[(c4 + 2) * KTST + r] = f2tf32(kv.z);
                kT[(c4 + 3) * KTST + r] = f2tf32(kv.w);
                uint4 vu = make_uint4(f2tf32(vv.x), f2tf32(vv.y), f2tf32(vv.z), f2tf32(vv.w));
                *(uint4*)&v[r * VST + c4] = vu;
            }
        }
        __syncthreads();

        // ---- warp-owned 16-row stripe ----
        int ri0 = rid[r0], ri1 = rid[r1];
        uint32_t aq[4][4];
        #pragma unroll
        for (int ks = 0; ks < 4; ks++) {
            int kk = ks << 3;
            aq[ks][0] = q[r0 * QST + kk + c];
            aq[ks][1] = q[r1 * QST + kk + c];
            aq[ks][2] = q[r0 * QST + kk + c + 4];
            aq[ks][3] = q[r1 * QST + kk + c + 4];
        }

        float s0 = 0.f, s1 = 0.f;
        #pragma unroll
        for (int nt = 0; nt < 13; nt++) {
            int n0 = nt << 3;
            float acc[4] = {0.f, 0.f, 0.f, 0.f};
            #pragma unroll
            for (int ks = 0; ks < 4; ks++) {
                int kk = ks << 3;
                uint32_t bf[2];
                bf[0] = kT[(kk + c) * KTST + n0 + g];
                bf[1] = kT[(kk + c + 4) * KTST + n0 + g];
                mma_tf32(acc, aq[ks], bf);
            }
            int col = n0 + 2 * c;
            int rj0 = rid[col], rj1 = rid[col + 1];
            float e0 = (ri0 == rj0) ? __expf(fminf(acc[0], 80.f)) : 0.f;
            float e1 = (ri0 == rj1) ? __expf(fminf(acc[1], 80.f)) : 0.f;
            float e2 = (ri1 == rj0) ? __expf(fminf(acc[2], 80.f)) : 0.f;
            float e3 = (ri1 == rj1) ? __expf(fminf(acc[3], 80.f)) : 0.f;
            s0 += e0 + e1;
            s1 += e2 + e3;
            pf[r0 * PST + col]     = __uint_as_float(f2tf32(e0));
            pf[r0 * PST + col + 1] = __uint_as_float(f2tf32(e1));
            pf[r1 * PST + col]     = __uint_as_float(f2tf32(e2));
            pf[r1 * PST + col + 1] = __uint_as_float(f2tf32(e3));
        }
        s0 += __shfl_xor_sync(0xffffffffu, s0, 1);
        s0 += __shfl_xor_sync(0xffffffffu, s0, 2);
        s1 += __shfl_xor_sync(0xffffffffu, s1, 1);
        s1 += __shfl_xor_sync(0xffffffffu, s1, 2);
        float rinv0 = 1.0f / s0;
        float rinv1 = 1.0f / s1;
        __syncwarp();

        #pragma unroll
        for (int nt = 0; nt < 4; nt++) {
            int d0 = nt << 3;
            float acc[4] = {0.f, 0.f, 0.f, 0.f};
            #pragma unroll
            for (int ks = 0; ks < 13; ks++) {
                int kk = ks << 3;
                uint32_t a[4], bf[2];
                a[0] = p[r0 * PST + kk + c];
                a[1] = p[r1 * PST + kk + c];
                a[2] = p[r0 * PST + kk + c + 4];
                a[3] = p[r1 * PST + kk + c + 4];
                bf[0] = v[(kk + c) * VST + d0 + g];
                bf[1] = v[(kk + c + 4) * VST + d0 + g];
                mma_tf32(acc, a, bf);
            }
            o_regs[h * 16 + nt * 4 + 0] = acc[0] * rinv0;
            o_regs[h * 16 + nt * 4 + 1] = acc[1] * rinv0;
            o_regs[h * 16 + nt * 4 + 2] = acc[2] * rinv1;
            o_regs[h * 16 + nt * 4 + 3] = acc[3] * rinv1;
        }
    }

    __syncthreads();   // all attention reads done; q..p region reusable

    // o_regs -> o smem (own rows only; warp-local visibility suffices,
    // but Bc load below is block-wide, so syncs still guard Bc).
    #pragma unroll
    for (int h = 0; h < 4; h++)
        #pragma unroll
        for (int nt = 0; nt < 4; nt++) {
            int col = h * 32 + nt * 8 + 2 * c;
            o[r0 * OST + col]     = f2tf32(o_regs[h * 16 + nt * 4 + 0]);
            o[r0 * OST + col + 1] = f2tf32(o_regs[h * 16 + nt * 4 + 1]);
            o[r1 * OST + col]     = f2tf32(o_regs[h * 16 + nt * 4 + 2]);
            o[r1 * OST + col + 1] = f2tf32(o_regs[h * 16 + nt * 4 + 3]);
        }

    // scatter offsets
    size_t off0 = 0, off1 = 0;
    if (r0 < VOL) off0 = src_off(b, bt, bh, bw, r0);
    if (r1 < VOL) off1 = src_off(b, bt, bh, bw, r1);

    // proj in 4 chunks of 32 output columns
    for (int chunk = 0; chunk < 4; chunk++) {
        if (chunk) __syncthreads();        // prior chunk's Bc reads done
        for (int idx = tid; idx < 1024; idx += 224) {
            int r = idx >> 3, c4 = (idx & 7) << 2;
            float4 b4 = *(const float4*)(w_proj + (size_t)r * 128 + chunk * 32 + c4);
            Bc[r * BCST + c4 + 0] = f2tf32(b4.x);
            Bc[r * BCST + c4 + 1] = f2tf32(b4.y);
            Bc[r * BCST + c4 + 2] = f2tf32(b4.z);
            Bc[r * BCST + c4 + 3] = f2tf32(b4.w);
        }
        __syncthreads();

        float pacc[4][4] = {};
        #pragma unroll
        for (int kst = 0; kst < 16; kst++) {
            int kk = kst << 3;
            uint32_t a[4];
            a[0] = o[r0 * OST + kk + c];
            a[1] = o[r1 * OST + kk + c];
            a[2] = o[r0 * OST + kk + c + 4];
            a[3] = o[r1 * OST + kk + c + 4];
            #pragma unroll
            for (int nt = 0; nt < 4; nt++) {
                uint32_t bf[2];
                bf[0] = Bc[(kk + c) * BCST + nt * 8 + g];
                bf[1] = Bc[(kk + c + 4) * BCST + nt * 8 + g];
                mma_tf32(pacc[nt], a, bf);
            }
        }
        #pragma unroll
        for (int nt = 0; nt < 4; nt++) {
            int col = chunk * 32 + nt * 8 + 2 * c;
            float2 bb = *(const float2*)(b_proj + col);
            if (r0 < VOL)
                *(float2*)(out + off0 + col) =
                    make_float2(pacc[nt][0] + bb.x, pacc[nt][1] + bb.y);
            if (r1 < VOL)
                *(float2*)(out + off1 + col) =
                    make_float2(pacc[nt][2] + bb.x, pacc[nt][3] + bb.y);
        }
    }
}

// ---------------------------------------------------------------------------
extern "C" void kernel_launch(void* const* d_in, const int* in_sizes, int n_in,
                              void* d_out, int out_size)
{
    const float* x      = (const float*)d_in[0];
    const float* gamma  = (const float*)d_in[1];
    const float* beta   = (const float*)d_in[2];
    const float* w_qkv  = (const float*)d_in[3];
    const float* w_proj = (const float*)d_in[4];
    const float* b_proj = (const float*)d_in[5];
    float* out = (float*)d_out;

    const int SMEM_QKV = (128 * AST + 32 * 136) * 4;   // 84992 B
    cudaFuncSetAttribute(qkv_ln_gemm, cudaFuncAttributeMaxDynamicSharedMemorySize, SMEM_QKV);
    const int SMEM_AP = AP_U32 * 4;                    // 94912 B
    cudaFuncSetAttribute(attn_proj, cudaFuncAttributeMaxDynamicSharedMemorySize, SMEM_AP);

    qkv_ln_gemm<<<784, 256, SMEM_QKV>>>(x, gamma, beta, w_qkv);
    attn_proj<<<B_ * NC, 224, SMEM_AP>>>(w_proj, b_proj, out);
}